// round 12
// baseline (speedup 1.0000x reference)
#include <cuda_runtime.h>
#include <cstdint>

#define NLINKS   10000
#define NPATHS   100000
#define PLEN     8
#define HDIM     32
#define RDIM     8
#define TROUNDS  8
#define EDGES    (NPATHS * PLEN)

typedef unsigned long long ULL;

// ---------------- scratch (no cudaMalloc allowed) ----------------
__device__ __align__(16) float g_link_state[NLINKS * HDIM];
__device__ __align__(16) float g_path_state[NPATHS * HDIM];
__device__ __align__(16) float g_hs[(size_t)EDGES * HDIM];   // [s][path][32]
__device__ __align__(16) float g_gi[NLINKS * 96];            // per-link gi precompute
__device__ int   g_lk[EDGES];                  // link per slot t = 8p+s
__device__ int   g_srow[EDGES];                // sorted pos -> row (s*NPATHS+p)
__device__ int   g_hist[NLINKS];
__device__ int   g_off[NLINKS + 1];
__device__ int   g_cur[NLINKS];

// ---------------- helpers ----------------
__device__ __forceinline__ ULL fma2(ULL a, ULL b, ULL c) {
    ULL d;
    asm("fma.rn.f32x2 %0, %1, %2, %3;" : "=l"(d) : "l"(a), "l"(b), "l"(c));
    return d;
}
__device__ __forceinline__ ULL pk(float lo, float hi) {
    ULL r;
    asm("mov.b64 %0, {%1, %2};" : "=l"(r) : "f"(lo), "f"(hi));
    return r;
}
__device__ __forceinline__ void up2(ULL v, float& lo, float& hi) {
    asm("mov.b64 {%0, %1}, %2;" : "=f"(lo), "=f"(hi) : "l"(v));
}
__device__ __forceinline__ float tanh_fast(float x) {
    float y;
    asm("tanh.approx.f32 %0, %1;" : "=f"(y) : "f"(x));
    return y;
}
__device__ __forceinline__ float sigmoid_fast(float x) {
    return fmaf(0.5f, tanh_fast(0.5f * x), 0.5f);
}

// ---------------- setup A: states, lk map, hist zero -----------------------
__global__ void k_setupA(const float* __restrict__ cap, const float* __restrict__ bw,
                         const int* __restrict__ paths, const int* __restrict__ seqs,
                         const int* __restrict__ links) {
    int i = blockIdx.x * blockDim.x + threadIdx.x;
    if (i < NPATHS * HDIM) g_path_state[i] = ((i & (HDIM - 1)) == 0) ? bw[i / HDIM] : 0.f;
    if (i < NLINKS * HDIM) g_link_state[i] = ((i & (HDIM - 1)) == 0) ? cap[i / HDIM] : 0.f;
    if (i < NLINKS) g_hist[i] = 0;
    if (i < EDGES) g_lk[paths[i] * PLEN + seqs[i]] = links[i];
}

// ---------------- gi matvec from link_state (round-0 only) -----------------
__device__ __forceinline__ void gi_warp(int w, int lane,
                                        const float* sWT, const float* sb) {
    float h = g_link_state[w * HDIM + lane];
    float a0 = sb[lane], a1 = sb[32 + lane], a2 = sb[64 + lane];
#pragma unroll
    for (int k = 0; k < 32; k++) {
        float hv = __shfl_sync(0xffffffffu, h, k);
        a0 += hv * sWT[k * 96 + lane];
        a1 += hv * sWT[k * 96 + 32 + lane];
        a2 += hv * sWT[k * 96 + 64 + lane];
    }
    g_gi[w * 96 + lane] = a0;
    g_gi[w * 96 + 32 + lane] = a1;
    g_gi[w * 96 + 64 + lane] = a2;
}

// ---------------- setup B: histogram + round-0 gi --------------------------
#define HB ((EDGES + 255) / 256)
#define GB ((NLINKS * 32 + 255) / 256)
__global__ __launch_bounds__(256) void k_setupB(
    const int* __restrict__ links,
    const float* __restrict__ pWih, const float* __restrict__ pbih,
    const float* __restrict__ pbhh) {
    if (blockIdx.x < HB) {
        int e = blockIdx.x * 256 + threadIdx.x;
        if (e < EDGES) atomicAdd(&g_hist[links[e]], 1);
        return;
    }
    __shared__ float sWT[HDIM * 96];
    __shared__ float sb[96];
    for (int i = threadIdx.x; i < 96 * HDIM; i += 256) {
        int j = i / HDIM, k = i % HDIM;
        sWT[k * 96 + j] = pWih[i];
    }
    for (int i = threadIdx.x; i < 96; i += 256)
        sb[i] = pbih[i] + (i < 64 ? pbhh[i] : 0.f);
    __syncthreads();
    int w = ((blockIdx.x - HB) * 256 + threadIdx.x) >> 5;
    int lane = threadIdx.x & 31;
    if (w < NLINKS) gi_warp(w, lane, sWT, sb);
}

// ---------------- scan (offsets + cursors) ---------------------------------
__global__ void k_scan() {
    __shared__ int part[1024];
    int tid = threadIdx.x;
    const int CH = (NLINKS + 1023) / 1024;
    int base = tid * CH;
    int s = 0;
    for (int i = 0; i < CH; i++) {
        int idx = base + i;
        if (idx < NLINKS) s += g_hist[idx];
    }
    part[tid] = s;
    __syncthreads();
    for (int off = 1; off < 1024; off <<= 1) {
        int add = (tid >= off) ? part[tid - off] : 0;
        __syncthreads();
        part[tid] += add;
        __syncthreads();
    }
    int run = (tid == 0) ? 0 : part[tid - 1];
    for (int i = 0; i < CH; i++) {
        int idx = base + i;
        if (idx < NLINKS) {
            g_off[idx] = run;
            g_cur[idx] = run;
            run += g_hist[idx];
        }
    }
    if (tid == 1023) g_off[NLINKS] = part[1023];
}

// ---------------- path GRU (dominant kernel) ----------------
// Lane = hidden dim. Warp handles 8 paths as 4 f32x2 pairs. Dot products
// accumulate fully inside registers (no hsum); weights via broadcast-free
// LDS.64 from a packed [k][96] smem table; old-h broadcast via 1KB/warp smem.
__global__ __launch_bounds__(256) void k_path(
    int build, const float* __restrict__ pWhh, const float* __restrict__ pbhh) {
    __shared__ ULL sW2[32 * 96];    // [k][jj] = pk(Whh[jj][k], Whh[jj][k]); 24 KB
    __shared__ ULL hP[8][128];      // per-warp old-h: [pair*32 + lane]; 8 KB

    int tid = threadIdx.x, lane = tid & 31, wid = tid >> 5;
    for (int i = tid; i < 32 * 96; i += 256) {
        int k = i / 96, jj = i - k * 96;
        float w = pWhh[jj * HDIM + k];
        sW2[i] = pk(w, w);
    }
    float bn = pbhh[64 + lane];
    __syncthreads();

    int wg = blockIdx.x * 8 + wid;          // global warp id
    int pbase = wg * 8;
    if (pbase >= NPATHS) return;            // NPATHS % 8 == 0: whole warps only
    ULL* myhP = hP[wid];

    // load h for the 8 paths (pairs)
    ULL h2[4];
#pragma unroll
    for (int q = 0; q < 4; q++) {
        float he = g_path_state[(pbase + 2 * q) * HDIM + lane];
        float ho = g_path_state[(pbase + 2 * q + 1) * HDIM + lane];
        h2[q] = pk(he, ho);
    }

    int lkE[4], lkO[4];
#pragma unroll
    for (int q = 0; q < 4; q++) {
        lkE[q] = g_lk[(pbase + 2 * q) * PLEN];
        lkO[q] = g_lk[(pbase + 2 * q + 1) * PLEN];
    }

#pragma unroll 1
    for (int s = 0; s < PLEN; s++) {
        // issue gi loads now; consumed only after the long k-loop (natural prefetch)
        ULL gr2[4], gz2[4], gn2[4];
#pragma unroll
        for (int q = 0; q < 4; q++) {
            const float* gE = &g_gi[lkE[q] * 96];
            const float* gO = &g_gi[lkO[q] * 96];
            gr2[q] = pk(__ldg(gE + lane), __ldg(gO + lane));
            gz2[q] = pk(__ldg(gE + 32 + lane), __ldg(gO + 32 + lane));
            gn2[q] = pk(__ldg(gE + 64 + lane), __ldg(gO + 64 + lane));
        }
        if (build && lane < 8) {
            int p = pbase + lane;
            int lk = g_lk[p * PLEN + s];
            int pos = atomicAdd(&g_cur[lk], 1);
            g_srow[pos] = s * NPATHS + p;
        }
        // prefetch next step's links
        if (s + 1 < PLEN) {
#pragma unroll
            for (int q = 0; q < 4; q++) {
                lkE[q] = g_lk[(pbase + 2 * q) * PLEN + s + 1];
                lkO[q] = g_lk[(pbase + 2 * q + 1) * PLEN + s + 1];
            }
        }

        // publish old h for broadcast reads (writes must complete before reads)
        __syncwarp();
#pragma unroll
        for (int q = 0; q < 4; q++) myhP[q * 32 + lane] = h2[q];
        __syncwarp();

        ULL ar[4] = {0, 0, 0, 0}, az[4] = {0, 0, 0, 0}, an[4] = {0, 0, 0, 0};
#pragma unroll
        for (int k = 0; k < 32; k++) {
            ULL wr = sW2[k * 96 + lane];
            ULL wz = sW2[k * 96 + 32 + lane];
            ULL wn = sW2[k * 96 + 64 + lane];
#pragma unroll
            for (int q = 0; q < 4; q++) {
                ULL hk = myhP[q * 32 + k];   // broadcast (all lanes same addr)
                ar[q] = fma2(hk, wr, ar[q]);
                az[q] = fma2(hk, wz, az[q]);
                an[q] = fma2(hk, wn, an[q]);
            }
        }

        // gates + blend + coalesced g_hs store (all lane-local)
#pragma unroll
        for (int q = 0; q < 4; q++) {
            float arE, arO, azE, azO, anE, anO;
            up2(ar[q], arE, arO);
            up2(az[q], azE, azO);
            up2(an[q], anE, anO);
            float grE, grO, gzE, gzO, gnE, gnO;
            up2(gr2[q], grE, grO);
            up2(gz2[q], gzE, gzO);
            up2(gn2[q], gnE, gnO);
            float hE, hO;
            up2(h2[q], hE, hO);

            float rE = sigmoid_fast(grE + arE);
            float zE = sigmoid_fast(gzE + azE);
            float nE = tanh_fast(gnE + rE * (anE + bn));
            float rO = sigmoid_fast(grO + arO);
            float zO = sigmoid_fast(gzO + azO);
            float nO = tanh_fast(gnO + rO * (anO + bn));

            float hnE = (1.f - zE) * nE + zE * hE;
            float hnO = (1.f - zO) * nO + zO * hO;
            h2[q] = pk(hnE, hnO);

            g_hs[((size_t)s * NPATHS + pbase + 2 * q) * HDIM + lane] = hnE;
            g_hs[((size_t)s * NPATHS + pbase + 2 * q + 1) * HDIM + lane] = hnO;
        }
    }

    // final hidden -> path_state
#pragma unroll
    for (int q = 0; q < 4; q++) {
        float hE, hO;
        up2(h2[q], hE, hO);
        g_path_state[(pbase + 2 * q) * HDIM + lane] = hE;
        g_path_state[(pbase + 2 * q + 1) * HDIM + lane] = hO;
    }
}

// ---------- link aggregation + link GRU + fused next-round gi --------------
__global__ __launch_bounds__(256) void k_link(
    int dogi,
    const float* __restrict__ lWih, const float* __restrict__ lWhh,
    const float* __restrict__ lbih, const float* __restrict__ lbhh,
    const float* __restrict__ pWih, const float* __restrict__ pbih,
    const float* __restrict__ pbhh) {
    __shared__ float sWihT[3 * HDIM * HDIM];  // [k][j]
    __shared__ float sWhhT[3 * HDIM * HDIM];
    __shared__ float sPT[3 * HDIM * HDIM];    // path Wih^T for gi
    __shared__ float sbi[96], sbh[96], sgb[96];

    for (int i = threadIdx.x; i < 3 * HDIM * HDIM; i += 256) {
        int j = i / HDIM, k = i % HDIM;
        sWihT[k * 96 + j] = lWih[i];
        sWhhT[k * 96 + j] = lWhh[i];
        sPT[k * 96 + j] = pWih[i];
    }
    for (int i = threadIdx.x; i < 96; i += 256) {
        sbi[i] = lbih[i];
        sbh[i] = lbhh[i];
        sgb[i] = pbih[i] + (i < 64 ? pbhh[i] : 0.f);
    }
    __syncthreads();

    int w = (blockIdx.x * 256 + threadIdx.x) >> 5;
    int lane = threadIdx.x & 31;
    if (w >= NLINKS) return;

    int b = g_off[w], e = g_off[w + 1];
    float x0 = 0.f, x1 = 0.f, x2s = 0.f, x3 = 0.f;
    int i = b;
    for (; i + 4 <= e; i += 4) {
        int r0 = g_srow[i], r1 = g_srow[i + 1], r2 = g_srow[i + 2], r3 = g_srow[i + 3];
        x0 += g_hs[(size_t)r0 * HDIM + lane];
        x1 += g_hs[(size_t)r1 * HDIM + lane];
        x2s += g_hs[(size_t)r2 * HDIM + lane];
        x3 += g_hs[(size_t)r3 * HDIM + lane];
    }
    for (; i < e; i++) x0 += g_hs[(size_t)g_srow[i] * HDIM + lane];
    float x = (x0 + x1) + (x2s + x3);

    float h = g_link_state[w * HDIM + lane];

    float air = sbi[lane], aiz = sbi[32 + lane], ain = sbi[64 + lane];
    float ahr = sbh[lane], ahz = sbh[32 + lane], ahn = sbh[64 + lane];
#pragma unroll
    for (int k = 0; k < 32; k++) {
        float xv = __shfl_sync(0xffffffffu, x, k);
        float hv = __shfl_sync(0xffffffffu, h, k);
        air += xv * sWihT[k * 96 + lane];
        aiz += xv * sWihT[k * 96 + 32 + lane];
        ain += xv * sWihT[k * 96 + 64 + lane];
        ahr += hv * sWhhT[k * 96 + lane];
        ahz += hv * sWhhT[k * 96 + 32 + lane];
        ahn += hv * sWhhT[k * 96 + 64 + lane];
    }
    float r = sigmoid_fast(air + ahr);
    float z = sigmoid_fast(aiz + ahz);
    float nv = tanh_fast(ain + r * ahn);
    float hnew = (1.f - z) * nv + z * h;
    g_link_state[w * HDIM + lane] = hnew;

    if (dogi) {
        float a0 = sgb[lane], a1 = sgb[32 + lane], a2 = sgb[64 + lane];
#pragma unroll
        for (int k = 0; k < 32; k++) {
            float hv = __shfl_sync(0xffffffffu, hnew, k);
            a0 += hv * sPT[k * 96 + lane];
            a1 += hv * sPT[k * 96 + 32 + lane];
            a2 += hv * sPT[k * 96 + 64 + lane];
        }
        g_gi[w * 96 + lane] = a0;
        g_gi[w * 96 + 32 + lane] = a1;
        g_gi[w * 96 + 64 + lane] = a2;
    }
}

// ---------------- readout MLP ----------------
__global__ __launch_bounds__(256) void k_readout(
    const float* __restrict__ W1, const float* __restrict__ b1,
    const float* __restrict__ W2, const float* __restrict__ b2,
    const float* __restrict__ W3, const float* __restrict__ b3,
    float* __restrict__ out) {
    __shared__ float s1[RDIM * HDIM], sb1[RDIM], s2[RDIM * RDIM], sb2[RDIM], s3[RDIM], sb3;
    for (int i = threadIdx.x; i < RDIM * HDIM; i += 256) s1[i] = W1[i];
    if (threadIdx.x < RDIM * RDIM) s2[threadIdx.x] = W2[threadIdx.x];
    if (threadIdx.x < RDIM) {
        sb1[threadIdx.x] = b1[threadIdx.x];
        sb2[threadIdx.x] = b2[threadIdx.x];
        s3[threadIdx.x] = W3[threadIdx.x];
    }
    if (threadIdx.x == 0) sb3 = b3[0];
    __syncthreads();

    int p = blockIdx.x * 256 + threadIdx.x;
    if (p >= NPATHS) return;

    float x[HDIM];
    {
        const float4* src = (const float4*)&g_path_state[p * HDIM];
#pragma unroll
        for (int i = 0; i < 8; i++) {
            float4 v = src[i];
            x[4 * i] = v.x; x[4 * i + 1] = v.y; x[4 * i + 2] = v.z; x[4 * i + 3] = v.w;
        }
    }
    float y1[RDIM];
#pragma unroll
    for (int i = 0; i < RDIM; i++) {
        float d = sb1[i];
#pragma unroll
        for (int k = 0; k < HDIM; k++) d += x[k] * s1[i * HDIM + k];
        y1[i] = fmaxf(d, 0.f);
    }
    float y2[RDIM];
#pragma unroll
    for (int i = 0; i < RDIM; i++) {
        float d = sb2[i];
#pragma unroll
        for (int k = 0; k < RDIM; k++) d += y1[k] * s2[i * RDIM + k];
        y2[i] = fmaxf(d, 0.f);
    }
    float o = sb3;
#pragma unroll
    for (int k = 0; k < RDIM; k++) o += y2[k] * s3[k];
    out[p] = o;
}

// ---------------- launch ----------------
extern "C" void kernel_launch(void* const* d_in, const int* in_sizes, int n_in,
                              void* d_out, int out_size) {
    const int* links = (const int*)d_in[0];
    const int* paths = (const int*)d_in[1];
    const int* seqs  = (const int*)d_in[2];
    const float* cap = (const float*)d_in[3];
    const float* bw  = (const float*)d_in[4];
    const float* pWih = (const float*)d_in[5];
    const float* pWhh = (const float*)d_in[6];
    const float* pbih = (const float*)d_in[7];
    const float* pbhh = (const float*)d_in[8];
    const float* lWih = (const float*)d_in[9];
    const float* lWhh = (const float*)d_in[10];
    const float* lbih = (const float*)d_in[11];
    const float* lbhh = (const float*)d_in[12];
    const float* W1 = (const float*)d_in[13];
    const float* b1 = (const float*)d_in[14];
    const float* W2 = (const float*)d_in[15];
    const float* b2 = (const float*)d_in[16];
    const float* W3 = (const float*)d_in[17];
    const float* b3 = (const float*)d_in[18];
    float* out = (float*)d_out;

    (void)in_sizes; (void)n_in; (void)out_size;

    k_setupA<<<(NPATHS * HDIM + 255) / 256, 256>>>(cap, bw, paths, seqs, links);
    k_setupB<<<HB + GB, 256>>>(links, pWih, pbih, pbhh);
    k_scan<<<1, 1024>>>();

    // warps = NPATHS/8 = 12500; 8 warps per CTA
    int pblocks = (NPATHS / 8 + 7) / 8;
    for (int r = 0; r < TROUNDS; r++) {
        k_path<<<pblocks, 256>>>(r == 0 ? 1 : 0, pWhh, pbhh);
        k_link<<<(NLINKS + 7) / 8, 256>>>(r + 1 < TROUNDS ? 1 : 0,
                                          lWih, lWhh, lbih, lbhh,
                                          pWih, pbih, pbhh);
    }
    k_readout<<<(NPATHS + 255) / 256, 256>>>(W1, b1, W2, b2, W3, b3, out);
}

// round 14
// speedup vs baseline: 1.5841x; 1.5841x over previous
#include <cuda_runtime.h>
#include <cstdint>

#define NLINKS   10000
#define NPATHS   100000
#define PLEN     8
#define HDIM     32
#define RDIM     8
#define TROUNDS  8
#define EDGES    (NPATHS * PLEN)

typedef unsigned long long ULL;

// ---------------- scratch (no cudaMalloc allowed) ----------------
__device__ __align__(16) float g_link_state[NLINKS * HDIM];
__device__ __align__(16) float g_path_state[NPATHS * HDIM];
__device__ __align__(16) float g_hs[(size_t)EDGES * HDIM];   // [s][path][32]
__device__ __align__(16) float g_gi[NLINKS * 96];            // per-link gi precompute
__device__ int   g_lk[EDGES];                  // link per slot t = 8p+s
__device__ int   g_srow[EDGES];                // sorted pos -> row (s*NPATHS+p)
__device__ int   g_hist[NLINKS];
__device__ int   g_off[NLINKS + 1];
__device__ int   g_cur[NLINKS];

// ---------------- helpers ----------------
__device__ __forceinline__ ULL fma2(ULL a, ULL b, ULL c) {
    ULL d;
    asm("fma.rn.f32x2 %0, %1, %2, %3;" : "=l"(d) : "l"(a), "l"(b), "l"(c));
    return d;
}
__device__ __forceinline__ ULL pk(float lo, float hi) {
    ULL r;
    asm("mov.b64 %0, {%1, %2};" : "=l"(r) : "f"(lo), "f"(hi));
    return r;
}
__device__ __forceinline__ float hsum2(ULL v) {
    float lo, hi;
    asm("mov.b64 {%0, %1}, %2;" : "=f"(lo), "=f"(hi) : "l"(v));
    return lo + hi;
}
__device__ __forceinline__ float tanh_fast(float x) {
    float y;
    asm("tanh.approx.f32 %0, %1;" : "=f"(y) : "f"(x));
    return y;
}
__device__ __forceinline__ float sigmoid_fast(float x) {
    return fmaf(0.5f, tanh_fast(0.5f * x), 0.5f);
}

// ---------------- setup A: states, lk map, hist zero -----------------------
__global__ void k_setupA(const float* __restrict__ cap, const float* __restrict__ bw,
                         const int* __restrict__ paths, const int* __restrict__ seqs,
                         const int* __restrict__ links) {
    int i = blockIdx.x * blockDim.x + threadIdx.x;
    if (i < NPATHS * HDIM) g_path_state[i] = ((i & (HDIM - 1)) == 0) ? bw[i / HDIM] : 0.f;
    if (i < NLINKS * HDIM) g_link_state[i] = ((i & (HDIM - 1)) == 0) ? cap[i / HDIM] : 0.f;
    if (i < NLINKS) g_hist[i] = 0;
    if (i < EDGES) g_lk[paths[i] * PLEN + seqs[i]] = links[i];
}

// ---------------- gi matvec from link_state (round-0 only) -----------------
__device__ __forceinline__ void gi_warp(int w, int lane,
                                        const float* sWT, const float* sb) {
    float h = g_link_state[w * HDIM + lane];
    float a0 = sb[lane], a1 = sb[32 + lane], a2 = sb[64 + lane];
#pragma unroll
    for (int k = 0; k < 32; k++) {
        float hv = __shfl_sync(0xffffffffu, h, k);
        a0 += hv * sWT[k * 96 + lane];
        a1 += hv * sWT[k * 96 + 32 + lane];
        a2 += hv * sWT[k * 96 + 64 + lane];
    }
    g_gi[w * 96 + lane] = a0;
    g_gi[w * 96 + 32 + lane] = a1;
    g_gi[w * 96 + 64 + lane] = a2;
}

// ---------------- setup B: histogram + round-0 gi --------------------------
#define HB ((EDGES + 255) / 256)
#define GB ((NLINKS * 32 + 255) / 256)
__global__ __launch_bounds__(256) void k_setupB(
    const int* __restrict__ links,
    const float* __restrict__ pWih, const float* __restrict__ pbih,
    const float* __restrict__ pbhh) {
    if (blockIdx.x < HB) {
        int e = blockIdx.x * 256 + threadIdx.x;
        if (e < EDGES) atomicAdd(&g_hist[links[e]], 1);
        return;
    }
    __shared__ float sWT[HDIM * 96];
    __shared__ float sb[96];
    for (int i = threadIdx.x; i < 96 * HDIM; i += 256) {
        int j = i / HDIM, k = i % HDIM;
        sWT[k * 96 + j] = pWih[i];
    }
    for (int i = threadIdx.x; i < 96; i += 256)
        sb[i] = pbih[i] + (i < 64 ? pbhh[i] : 0.f);
    __syncthreads();
    int w = ((blockIdx.x - HB) * 256 + threadIdx.x) >> 5;
    int lane = threadIdx.x & 31;
    if (w < NLINKS) gi_warp(w, lane, sWT, sb);
}

// ---------------- scan (offsets + cursors) ---------------------------------
__global__ void k_scan() {
    __shared__ int part[1024];
    int tid = threadIdx.x;
    const int CH = (NLINKS + 1023) / 1024;
    int base = tid * CH;
    int s = 0;
    for (int i = 0; i < CH; i++) {
        int idx = base + i;
        if (idx < NLINKS) s += g_hist[idx];
    }
    part[tid] = s;
    __syncthreads();
    for (int off = 1; off < 1024; off <<= 1) {
        int add = (tid >= off) ? part[tid - off] : 0;
        __syncthreads();
        part[tid] += add;
        __syncthreads();
    }
    int run = (tid == 0) ? 0 : part[tid - 1];
    for (int i = 0; i < CH; i++) {
        int idx = base + i;
        if (idx < NLINKS) {
            g_off[idx] = run;
            g_cur[idx] = run;
            run += g_hist[idx];
        }
    }
    if (tid == 1023) g_off[NLINKS] = part[1023];
}

// ---------------- path GRU (dominant kernel) ----------------
// Lane = hidden dim j. Warp handles 16 paths. fma2 packs CONSECUTIVE K PAIRS
// (not paths) -> weight table needs no duplication (half the smem bytes);
// h[k..k+3] comes as one LDS.128 broadcast per path per k4.
// gi folds into accumulator init (lo half), so it costs no extra registers.
__global__ __launch_bounds__(128) void k_path(
    int build, const float* __restrict__ pWhh, const float* __restrict__ pbhh) {
    __shared__ __align__(16) ulonglong2 sWv[8][3][32];  // [k4][gate][jj]; 12 KB
    __shared__ __align__(16) float hPs[4][16 * 32];     // per-warp old/new h; 8 KB
    __shared__ int sLks[4][16];

    int tid = threadIdx.x, lane = tid & 31, wid = tid >> 5;
    // build packed weight table: .x = pk(W[row][4k4], W[row][4k4+1]), .y = next pair
    for (int i = tid; i < 768; i += 128) {
        int k4 = i / 96;
        int rem = i - k4 * 96;
        int g = rem >> 5, jj = rem & 31;
        const float* wrow = pWhh + (g * 32 + jj) * HDIM + k4 * 4;
        ulonglong2 v;
        v.x = pk(wrow[0], wrow[1]);
        v.y = pk(wrow[2], wrow[3]);
        sWv[k4][g][jj] = v;
    }
    float bn = pbhh[64 + lane];
    __syncthreads();

    int wg = blockIdx.x * 4 + wid;
    int pbase = wg * 16;                 // NPATHS = 16 * 6250 exactly
    if (pbase >= NPATHS) return;
    float* hP = hPs[wid];
    int* myLk = sLks[wid];

    // load initial hidden into the per-warp smem slab (lane j owns h[p][j])
#pragma unroll
    for (int p = 0; p < 16; p++)
        hP[p * 32 + lane] = g_path_state[(pbase + p) * HDIM + lane];
    __syncwarp();

#pragma unroll 1
    for (int s = 0; s < PLEN; s++) {
        if (lane < 16) myLk[lane] = g_lk[(pbase + lane) * PLEN + s];
        __syncwarp();

        // accumulators: lo sums even-k, hi odd-k; gi_r/gi_z/bn pre-folded in lo
        ULL aR[16], aZ[16], aN[16];
        float gn[16];
#pragma unroll
        for (int p = 0; p < 16; p++) {
            const float* gp = &g_gi[myLk[p] * 96];
            aR[p] = pk(__ldg(gp + lane), 0.f);
            aZ[p] = pk(__ldg(gp + 32 + lane), 0.f);
            aN[p] = pk(bn, 0.f);
            gn[p] = __ldg(gp + 64 + lane);
        }
        if (build && lane < 16) {
            int pos = atomicAdd(&g_cur[myLk[lane]], 1);
            g_srow[pos] = s * NPATHS + pbase + lane;
        }

#pragma unroll
        for (int k4 = 0; k4 < 8; k4++) {
            ulonglong2 wR = sWv[k4][0][lane];
            ulonglong2 wZ = sWv[k4][1][lane];
            ulonglong2 wN = sWv[k4][2][lane];
#pragma unroll
            for (int p = 0; p < 16; p++) {
                ulonglong2 hv = *(const ulonglong2*)&hP[p * 32 + k4 * 4];  // broadcast
                aR[p] = fma2(hv.x, wR.x, aR[p]);
                aR[p] = fma2(hv.y, wR.y, aR[p]);
                aZ[p] = fma2(hv.x, wZ.x, aZ[p]);
                aZ[p] = fma2(hv.y, wZ.y, aZ[p]);
                aN[p] = fma2(hv.x, wN.x, aN[p]);
                aN[p] = fma2(hv.y, wN.y, aN[p]);
            }
        }
        __syncwarp();  // all k-loop reads of hP complete before epilogue overwrites

        // gates + blend + coalesced stores (lane-local); overwrite hP with new h
#pragma unroll
        for (int p = 0; p < 16; p++) {
            float r = sigmoid_fast(hsum2(aR[p]));
            float z = sigmoid_fast(hsum2(aZ[p]));
            float n = tanh_fast(gn[p] + r * hsum2(aN[p]));
            float hold = hP[p * 32 + lane];
            float hn = (1.f - z) * n + z * hold;
            g_hs[((size_t)s * NPATHS + pbase + p) * HDIM + lane] = hn;
            hP[p * 32 + lane] = hn;
        }
        __syncwarp();  // new h visible cross-lane before next step's broadcasts
    }

    // final hidden -> path_state
#pragma unroll
    for (int p = 0; p < 16; p++)
        g_path_state[(pbase + p) * HDIM + lane] = hP[p * 32 + lane];
}

// ---------- link aggregation + link GRU + fused next-round gi --------------
__global__ __launch_bounds__(256) void k_link(
    int dogi,
    const float* __restrict__ lWih, const float* __restrict__ lWhh,
    const float* __restrict__ lbih, const float* __restrict__ lbhh,
    const float* __restrict__ pWih, const float* __restrict__ pbih,
    const float* __restrict__ pbhh) {
    __shared__ float sWihT[3 * HDIM * HDIM];  // [k][j]
    __shared__ float sWhhT[3 * HDIM * HDIM];
    __shared__ float sPT[3 * HDIM * HDIM];    // path Wih^T for gi
    __shared__ float sbi[96], sbh[96], sgb[96];

    for (int i = threadIdx.x; i < 3 * HDIM * HDIM; i += 256) {
        int j = i / HDIM, k = i % HDIM;
        sWihT[k * 96 + j] = lWih[i];
        sWhhT[k * 96 + j] = lWhh[i];
        sPT[k * 96 + j] = pWih[i];
    }
    for (int i = threadIdx.x; i < 96; i += 256) {
        sbi[i] = lbih[i];
        sbh[i] = lbhh[i];
        sgb[i] = pbih[i] + (i < 64 ? pbhh[i] : 0.f);
    }
    __syncthreads();

    int w = (blockIdx.x * 256 + threadIdx.x) >> 5;
    int lane = threadIdx.x & 31;
    if (w >= NLINKS) return;

    int b = g_off[w], e = g_off[w + 1];
    float x0 = 0.f, x1 = 0.f, x2s = 0.f, x3 = 0.f;
    int i = b;
    for (; i + 4 <= e; i += 4) {
        int r0 = g_srow[i], r1 = g_srow[i + 1], r2 = g_srow[i + 2], r3 = g_srow[i + 3];
        x0 += g_hs[(size_t)r0 * HDIM + lane];
        x1 += g_hs[(size_t)r1 * HDIM + lane];
        x2s += g_hs[(size_t)r2 * HDIM + lane];
        x3 += g_hs[(size_t)r3 * HDIM + lane];
    }
    for (; i < e; i++) x0 += g_hs[(size_t)g_srow[i] * HDIM + lane];
    float x = (x0 + x1) + (x2s + x3);

    float h = g_link_state[w * HDIM + lane];

    float air = sbi[lane], aiz = sbi[32 + lane], ain = sbi[64 + lane];
    float ahr = sbh[lane], ahz = sbh[32 + lane], ahn = sbh[64 + lane];
#pragma unroll
    for (int k = 0; k < 32; k++) {
        float xv = __shfl_sync(0xffffffffu, x, k);
        float hv = __shfl_sync(0xffffffffu, h, k);
        air += xv * sWihT[k * 96 + lane];
        aiz += xv * sWihT[k * 96 + 32 + lane];
        ain += xv * sWihT[k * 96 + 64 + lane];
        ahr += hv * sWhhT[k * 96 + lane];
        ahz += hv * sWhhT[k * 96 + 32 + lane];
        ahn += hv * sWhhT[k * 96 + 64 + lane];
    }
    float r = sigmoid_fast(air + ahr);
    float z = sigmoid_fast(aiz + ahz);
    float nv = tanh_fast(ain + r * ahn);
    float hnew = (1.f - z) * nv + z * h;
    g_link_state[w * HDIM + lane] = hnew;

    if (dogi) {
        float a0 = sgb[lane], a1 = sgb[32 + lane], a2 = sgb[64 + lane];
#pragma unroll
        for (int k = 0; k < 32; k++) {
            float hv = __shfl_sync(0xffffffffu, hnew, k);
            a0 += hv * sPT[k * 96 + lane];
            a1 += hv * sPT[k * 96 + 32 + lane];
            a2 += hv * sPT[k * 96 + 64 + lane];
        }
        g_gi[w * 96 + lane] = a0;
        g_gi[w * 96 + 32 + lane] = a1;
        g_gi[w * 96 + 64 + lane] = a2;
    }
}

// ---------------- readout MLP ----------------
__global__ __launch_bounds__(256) void k_readout(
    const float* __restrict__ W1, const float* __restrict__ b1,
    const float* __restrict__ W2, const float* __restrict__ b2,
    const float* __restrict__ W3, const float* __restrict__ b3,
    float* __restrict__ out) {
    __shared__ float s1[RDIM * HDIM], sb1[RDIM], s2[RDIM * RDIM], sb2[RDIM], s3[RDIM], sb3;
    for (int i = threadIdx.x; i < RDIM * HDIM; i += 256) s1[i] = W1[i];
    if (threadIdx.x < RDIM * RDIM) s2[threadIdx.x] = W2[threadIdx.x];
    if (threadIdx.x < RDIM) {
        sb1[threadIdx.x] = b1[threadIdx.x];
        sb2[threadIdx.x] = b2[threadIdx.x];
        s3[threadIdx.x] = W3[threadIdx.x];
    }
    if (threadIdx.x == 0) sb3 = b3[0];
    __syncthreads();

    int p = blockIdx.x * 256 + threadIdx.x;
    if (p >= NPATHS) return;

    float x[HDIM];
    {
        const float4* src = (const float4*)&g_path_state[p * HDIM];
#pragma unroll
        for (int i = 0; i < 8; i++) {
            float4 v = src[i];
            x[4 * i] = v.x; x[4 * i + 1] = v.y; x[4 * i + 2] = v.z; x[4 * i + 3] = v.w;
        }
    }
    float y1[RDIM];
#pragma unroll
    for (int i = 0; i < RDIM; i++) {
        float d = sb1[i];
#pragma unroll
        for (int k = 0; k < HDIM; k++) d += x[k] * s1[i * HDIM + k];
        y1[i] = fmaxf(d, 0.f);
    }
    float y2[RDIM];
#pragma unroll
    for (int i = 0; i < RDIM; i++) {
        float d = sb2[i];
#pragma unroll
        for (int k = 0; k < RDIM; k++) d += y1[k] * s2[i * RDIM + k];
        y2[i] = fmaxf(d, 0.f);
    }
    float o = sb3;
#pragma unroll
    for (int k = 0; k < RDIM; k++) o += y2[k] * s3[k];
    out[p] = o;
}

// ---------------- launch ----------------
extern "C" void kernel_launch(void* const* d_in, const int* in_sizes, int n_in,
                              void* d_out, int out_size) {
    const int* links = (const int*)d_in[0];
    const int* paths = (const int*)d_in[1];
    const int* seqs  = (const int*)d_in[2];
    const float* cap = (const float*)d_in[3];
    const float* bw  = (const float*)d_in[4];
    const float* pWih = (const float*)d_in[5];
    const float* pWhh = (const float*)d_in[6];
    const float* pbih = (const float*)d_in[7];
    const float* pbhh = (const float*)d_in[8];
    const float* lWih = (const float*)d_in[9];
    const float* lWhh = (const float*)d_in[10];
    const float* lbih = (const float*)d_in[11];
    const float* lbhh = (const float*)d_in[12];
    const float* W1 = (const float*)d_in[13];
    const float* b1 = (const float*)d_in[14];
    const float* W2 = (const float*)d_in[15];
    const float* b2 = (const float*)d_in[16];
    const float* W3 = (const float*)d_in[17];
    const float* b3 = (const float*)d_in[18];
    float* out = (float*)d_out;

    (void)in_sizes; (void)n_in; (void)out_size;

    k_setupA<<<(NPATHS * HDIM + 255) / 256, 256>>>(cap, bw, paths, seqs, links);
    k_setupB<<<HB + GB, 256>>>(links, pWih, pbih, pbhh);
    k_scan<<<1, 1024>>>();

    // warps = NPATHS/16 = 6250; 4 warps per CTA
    int pblocks = (NPATHS / 16 + 3) / 4;
    for (int r = 0; r < TROUNDS; r++) {
        k_path<<<pblocks, 128>>>(r == 0 ? 1 : 0, pWhh, pbhh);
        k_link<<<(NLINKS + 7) / 8, 256>>>(r + 1 < TROUNDS ? 1 : 0,
                                          lWih, lWhh, lbih, lbhh,
                                          pWih, pbih, pbhh);
    }
    k_readout<<<(NPATHS + 255) / 256, 256>>>(W1, b1, W2, b2, W3, b3, out);
}